// round 5
// baseline (speedup 1.0000x reference)
#include <cuda_runtime.h>
#include <cuda_bf16.h>
#include <cuda_fp8.h>
#include <cstdint>

#define SMOOTH 0.1f
#define NROWS 4096
#define VOCAB 32000
#define DIM   1024
#define CTILES 250   /* VOCAB/128 */
#define RTILES 32    /* NROWS/128 */
#define KS 64        /* K bytes (=elems, fp8) per stage */
#define NKT (DIM / KS) /* 16 */

// x scaled by 4, W scaled by 64 -> logits = accum / 256
#define XSCALE 4.0f
#define WSCALE 64.0f
#define INV_SCALE 0.00390625f  /* 1/256 */

// ---- scratch (__device__ globals: allocation-free) ----
__device__ uint8_t g_xq[(size_t)NROWS * DIM];   // 4 MB  (e4m3 of 4*x)
__device__ uint8_t g_Wq[(size_t)VOCAB * DIM];   // 32 MB (e4m3 of 64*W)
__device__ float g_pExp[(size_t)CTILES * NROWS];
__device__ float g_pLog[(size_t)CTILES * NROWS];
__device__ float g_ly[NROWS];
__device__ float g_rv[NROWS];

// ---------------- converts: f32 -> e4m3 (scaled) ----------------
__global__ void cvt_x_kernel(const float* __restrict__ s) {
    size_t i = ((size_t)blockIdx.x * blockDim.x + threadIdx.x) * 4;
    float4 v = *(const float4*)(s + i);
    uchar4 o;
    o.x = __nv_cvt_float_to_fp8(v.x * XSCALE, __NV_SATFINITE, __NV_E4M3);
    o.y = __nv_cvt_float_to_fp8(v.y * XSCALE, __NV_SATFINITE, __NV_E4M3);
    o.z = __nv_cvt_float_to_fp8(v.z * XSCALE, __NV_SATFINITE, __NV_E4M3);
    o.w = __nv_cvt_float_to_fp8(v.w * XSCALE, __NV_SATFINITE, __NV_E4M3);
    *reinterpret_cast<uchar4*>(&g_xq[i]) = o;
}
__global__ void cvt_w_kernel(const float* __restrict__ s) {
    size_t i = ((size_t)blockIdx.x * blockDim.x + threadIdx.x) * 4;
    float4 v = *(const float4*)(s + i);
    uchar4 o;
    o.x = __nv_cvt_float_to_fp8(v.x * WSCALE, __NV_SATFINITE, __NV_E4M3);
    o.y = __nv_cvt_float_to_fp8(v.y * WSCALE, __NV_SATFINITE, __NV_E4M3);
    o.z = __nv_cvt_float_to_fp8(v.z * WSCALE, __NV_SATFINITE, __NV_E4M3);
    o.w = __nv_cvt_float_to_fp8(v.w * WSCALE, __NV_SATFINITE, __NV_E4M3);
    *reinterpret_cast<uchar4*>(&g_Wq[i]) = o;
}

// ---------------- GEMM (fp8 QMMA) + fused LSE partials ----------------
__device__ __forceinline__ void cp16(void* sdst, const void* gsrc) {
    unsigned sa = (unsigned)__cvta_generic_to_shared(sdst);
    asm volatile("cp.async.cg.shared.global [%0], [%1], 16;\n" :: "r"(sa), "l"(gsrc));
}

__global__ void __launch_bounds__(256) gemm_lse_kernel() {
    // row stride 80 B: 64 B data + 16 B pad; 8 rows at stride 80 cover distinct
    // 16B slots mod 128 -> ldmatrix conflict-free; 16B-aligned for cp.async.
    constexpr int LDS = 80;
    __shared__ __align__(16) uint8_t As[2][128 * LDS];
    __shared__ __align__(16) uint8_t Bs[2][128 * LDS];
    __shared__ float redE[128][4];
    __shared__ float redL[128][4];

    const int tid  = threadIdx.x;
    const int lane = tid & 31;
    const int warp = tid >> 5;
    const int ct = blockIdx.x, rt = blockIdx.y;
    const int m0 = rt * 128, n0 = ct * 128;
    const int wm0 = (warp & 1) * 64;  // 2 warps in M
    const int wn  = warp >> 1;        // 4 warps in N
    const int wn0 = wn * 32;

    float c[4][4][4];
#pragma unroll
    for (int i = 0; i < 4; i++)
#pragma unroll
        for (int j = 0; j < 4; j++)
#pragma unroll
            for (int k = 0; k < 4; k++) c[i][j][k] = 0.f;

    auto load_stage = [&](int st, int k0) {
        // 128 rows x 4 x 16B chunks each for A and B (512 chunks, 2 iters)
#pragma unroll
        for (int cc = tid; cc < 512; cc += 256) {
            int row = cc >> 2, col = (cc & 3) << 4;
            cp16(&As[st][row * LDS + col], &g_xq[(size_t)(m0 + row) * DIM + k0 + col]);
        }
#pragma unroll
        for (int cc = tid; cc < 512; cc += 256) {
            int row = cc >> 2, col = (cc & 3) << 4;
            cp16(&Bs[st][row * LDS + col], &g_Wq[(size_t)(n0 + row) * DIM + k0 + col]);
        }
        asm volatile("cp.async.commit_group;\n");
    };

    load_stage(0, 0);

    // ldmatrix per-lane addressing (byte offsets)
    const int arow = lane & 15;            // A: row within 16-row frag
    const int ahalf = (lane >> 4) * 16;    // A: 16B half (k 0-15 / 16-31)
    const int brow = lane & 7;             // B: n-row within 8-row frag
    const int bhalf = ((lane >> 3) & 1) * 16;  // B: k half (lanes 0-15 used)

    for (int kt = 0; kt < NKT; kt++) {
        if (kt + 1 < NKT) {
            load_stage((kt + 1) & 1, (kt + 1) * KS);
            asm volatile("cp.async.wait_group 1;\n");
        } else {
            asm volatile("cp.async.wait_group 0;\n");
        }
        __syncthreads();
        const int st = kt & 1;
#pragma unroll
        for (int kk = 0; kk < 2; kk++) {  // two k32 steps per 64B stage
            uint32_t a[4][4], b[4][2];
#pragma unroll
            for (int mf = 0; mf < 4; mf++) {
                unsigned addr = (unsigned)__cvta_generic_to_shared(
                    &As[st][(wm0 + mf * 16 + arow) * LDS + kk * 32 + ahalf]);
                asm volatile("ldmatrix.sync.aligned.m8n8.x4.shared.b16 {%0,%1,%2,%3}, [%4];\n"
                             : "=r"(a[mf][0]), "=r"(a[mf][1]), "=r"(a[mf][2]), "=r"(a[mf][3])
                             : "r"(addr));
            }
#pragma unroll
            for (int nf = 0; nf < 4; nf++) {
                unsigned addr = (unsigned)__cvta_generic_to_shared(
                    &Bs[st][(wn0 + nf * 8 + brow) * LDS + kk * 32 + bhalf]);
                asm volatile("ldmatrix.sync.aligned.m8n8.x2.shared.b16 {%0,%1}, [%2];\n"
                             : "=r"(b[nf][0]), "=r"(b[nf][1])
                             : "r"(addr));
            }
#pragma unroll
            for (int mf = 0; mf < 4; mf++)
#pragma unroll
                for (int nf = 0; nf < 4; nf++) {
                    asm volatile(
                        "mma.sync.aligned.m16n8k32.row.col.f32.e4m3.e4m3.f32 "
                        "{%0,%1,%2,%3}, {%4,%5,%6,%7}, {%8,%9}, {%0,%1,%2,%3};\n"
                        : "+f"(c[mf][nf][0]), "+f"(c[mf][nf][1]),
                          "+f"(c[mf][nf][2]), "+f"(c[mf][nf][3])
                        : "r"(a[mf][0]), "r"(a[mf][1]), "r"(a[mf][2]), "r"(a[mf][3]),
                          "r"(b[nf][0]), "r"(b[nf][1]));
                }
        }
        __syncthreads();
    }

    // fused epilogue: per-row sum(exp(logit)), sum(logit); logit = c/256.
#pragma unroll
    for (int mf = 0; mf < 4; mf++)
#pragma unroll
        for (int r = 0; r < 2; r++) {
            float se = 0.f, sl = 0.f;
#pragma unroll
            for (int nf = 0; nf < 4; nf++)
#pragma unroll
                for (int j = 0; j < 2; j++) {
                    float v = c[mf][nf][r * 2 + j] * INV_SCALE;
                    se += __expf(v);
                    sl += v;
                }
            se += __shfl_xor_sync(0xffffffffu, se, 1);
            sl += __shfl_xor_sync(0xffffffffu, sl, 1);
            se += __shfl_xor_sync(0xffffffffu, se, 2);
            sl += __shfl_xor_sync(0xffffffffu, sl, 2);
            if ((lane & 3) == 0) {
                int row = wm0 + mf * 16 + r * 8 + (lane >> 2);
                redE[row][wn] = se;
                redL[row][wn] = sl;
            }
        }
    __syncthreads();
    if (tid < 128) {
        float e = redE[tid][0] + redE[tid][1] + redE[tid][2] + redE[tid][3];
        float l = redL[tid][0] + redL[tid][1] + redL[tid][2] + redL[tid][3];
        g_pExp[(size_t)ct * NROWS + m0 + tid] = e;
        g_pLog[(size_t)ct * NROWS + m0 + tid] = l;
    }
}

// ---------------- gathered target logit, fp32 exact path ----------------
__global__ void gatherdot_kernel(const float* __restrict__ x,
                                 const float* __restrict__ W,
                                 const int* __restrict__ y32) {
    int n = blockIdx.x, tid = threadIdx.x;  // 128 threads
    bool is64 = (y32[1] == 0) && (y32[3] == 0) && (y32[5] == 0) && (y32[7] == 0);
    int idx = is64 ? y32[2 * n] : y32[n];
    if (idx < 0) idx = 0;
    if (idx >= VOCAB) idx = VOCAB - 1;
    const float* xr = x + (size_t)n * DIM;
    const float* wr = W + (size_t)idx * DIM;
    float s = 0.f;
    for (int d = tid; d < DIM; d += 128) s += xr[d] * wr[d];
#pragma unroll
    for (int o = 16; o; o >>= 1) s += __shfl_xor_sync(0xffffffffu, s, o);
    __shared__ float sm[4];
    if ((tid & 31) == 0) sm[tid >> 5] = s;
    __syncthreads();
    if (tid == 0) g_ly[n] = sm[0] + sm[1] + sm[2] + sm[3];
}

// ---------------- per-row reduce over column tiles ----------------
__global__ void rowreduce_kernel() {
    int n = blockIdx.x * 256 + threadIdx.x;
    float e = 0.f, l = 0.f;
    for (int t = 0; t < CTILES; t++) {
        e += g_pExp[(size_t)t * NROWS + n];
        l += g_pLog[(size_t)t * NROWS + n];
    }
    g_rv[n] = logf(e) - (1.0f - SMOOTH) * g_ly[n] - (SMOOTH / (float)VOCAB) * l;
}

// ---------------- deterministic final scalar reduce ----------------
__global__ void final_kernel(float* __restrict__ out) {
    int tid = threadIdx.x;
    double s = 0.0;
    for (int i = tid; i < NROWS; i += 1024) s += (double)g_rv[i];
#pragma unroll
    for (int o = 16; o; o >>= 1) s += __shfl_xor_sync(0xffffffffu, s, o);
    __shared__ double sm[32];
    if ((tid & 31) == 0) sm[tid >> 5] = s;
    __syncthreads();
    if (tid < 32) {
        double v = sm[tid];
#pragma unroll
        for (int o = 16; o; o >>= 1) v += __shfl_xor_sync(0xffffffffu, v, o);
        if (tid == 0) out[0] = (float)(v / (double)NROWS);
    }
}

extern "C" void kernel_launch(void* const* d_in, const int* in_sizes, int n_in,
                              void* d_out, int out_size) {
    const float* x = nullptr;
    const float* W = nullptr;
    const int*   y = nullptr;
    for (int i = 0; i < n_in; i++) {
        if (in_sizes[i] == VOCAB * DIM)      W = (const float*)d_in[i];
        else if (in_sizes[i] == NROWS * DIM) x = (const float*)d_in[i];
        else if (in_sizes[i] == NROWS)       y = (const int*)d_in[i];
    }

    gatherdot_kernel<<<NROWS, 128>>>(x, W, y);
    cvt_x_kernel<<<(NROWS * DIM) / (256 * 4), 256>>>(x);
    cvt_w_kernel<<<(VOCAB * DIM) / (256 * 4), 256>>>(W);
    gemm_lse_kernel<<<dim3(CTILES, RTILES), 256>>>();
    rowreduce_kernel<<<NROWS / 256, 256>>>();
    final_kernel<<<1, 1024>>>((float*)d_out);
}

// round 6
// speedup vs baseline: 1.3051x; 1.3051x over previous
#include <cuda_runtime.h>
#include <cuda_bf16.h>
#include <cuda_fp8.h>
#include <cstdint>

#define SMOOTH 0.1f
#define NROWS 4096
#define VOCAB 32000
#define DIM   1024
#define CTILES 250   /* VOCAB/128 */
#define RTILES 32    /* NROWS/128 */
#define KS 128       /* K bytes (=elems, fp8) per stage */
#define NKT (DIM / KS) /* 8 */

// x scaled by 4, W scaled by 64 -> logits = accum / 256
#define XSCALE 4.0f
#define WSCALE 64.0f
#define INV_SCALE 0.00390625f  /* 1/256 */

// smem layout (dynamic): per stage A(128x144) + B(128x144)
#define LDSZ 144u
#define TILE_BYTES (128u * LDSZ)          /* 18432 */
#define STAGE_BYTES (2u * TILE_BYTES)     /* 36864 */
#define RED_OFF (2u * STAGE_BYTES)        /* 73728 */
#define SMEM_DYN (RED_OFF + 4096u)        /* + redE/redL 128x4 floats each */

// ---- scratch (__device__ globals: allocation-free) ----
__device__ uint8_t g_xq[(size_t)NROWS * DIM];   // 4 MB  (e4m3 of 4*x)
__device__ uint8_t g_Wq[(size_t)VOCAB * DIM];   // 32 MB (e4m3 of 64*W)
__device__ float g_pExp[(size_t)CTILES * NROWS];
__device__ float g_pLog[(size_t)CTILES * NROWS];
__device__ float g_ly[NROWS];
__device__ float g_rv[NROWS];

// ---------------- converts: f32 -> e4m3 (scaled) ----------------
__global__ void cvt_x_kernel(const float* __restrict__ s) {
    size_t i = ((size_t)blockIdx.x * blockDim.x + threadIdx.x) * 4;
    float4 v = *(const float4*)(s + i);
    uchar4 o;
    o.x = __nv_cvt_float_to_fp8(v.x * XSCALE, __NV_SATFINITE, __NV_E4M3);
    o.y = __nv_cvt_float_to_fp8(v.y * XSCALE, __NV_SATFINITE, __NV_E4M3);
    o.z = __nv_cvt_float_to_fp8(v.z * XSCALE, __NV_SATFINITE, __NV_E4M3);
    o.w = __nv_cvt_float_to_fp8(v.w * XSCALE, __NV_SATFINITE, __NV_E4M3);
    *reinterpret_cast<uchar4*>(&g_xq[i]) = o;
}
__global__ void cvt_w_kernel(const float* __restrict__ s) {
    size_t i = ((size_t)blockIdx.x * blockDim.x + threadIdx.x) * 4;
    float4 v = *(const float4*)(s + i);
    uchar4 o;
    o.x = __nv_cvt_float_to_fp8(v.x * WSCALE, __NV_SATFINITE, __NV_E4M3);
    o.y = __nv_cvt_float_to_fp8(v.y * WSCALE, __NV_SATFINITE, __NV_E4M3);
    o.z = __nv_cvt_float_to_fp8(v.z * WSCALE, __NV_SATFINITE, __NV_E4M3);
    o.w = __nv_cvt_float_to_fp8(v.w * WSCALE, __NV_SATFINITE, __NV_E4M3);
    *reinterpret_cast<uchar4*>(&g_Wq[i]) = o;
}

// ---------------- GEMM (fp8 QMMA) + fused LSE partials ----------------
__device__ __forceinline__ void cp16(uint32_t sdst, const void* gsrc) {
    asm volatile("cp.async.cg.shared.global [%0], [%1], 16;\n" :: "r"(sdst), "l"(gsrc));
}

__global__ void __launch_bounds__(256, 2) gemm_lse_kernel() {
    extern __shared__ __align__(16) uint8_t dsm[];
    const uint32_t smem0 = (uint32_t)__cvta_generic_to_shared(dsm);

    const int tid  = threadIdx.x;
    const int lane = tid & 31;
    const int warp = tid >> 5;
    const int ct = blockIdx.x, rt = blockIdx.y;
    const int m0 = rt * 128, n0 = ct * 128;
    const int wm0 = (warp & 1) * 64;  // 2 warps in M
    const int wn  = warp >> 1;        // 4 warps in N
    const int wn0 = wn * 32;

    float c[4][4][4];
#pragma unroll
    for (int i = 0; i < 4; i++)
#pragma unroll
        for (int j = 0; j < 4; j++)
#pragma unroll
            for (int k = 0; k < 4; k++) c[i][j][k] = 0.f;

    // hoisted ldmatrix byte offsets (row stride 144: 8 rows -> distinct 16B slots mod 128)
    const int arow = lane & 15;
    const int ahalf = (lane >> 4) * 16;
    const int brow = lane & 7;
    const int bhalf = ((lane >> 3) & 1) * 16;
    uint32_t aoff[4], boff[4];
#pragma unroll
    for (int mf = 0; mf < 4; mf++)
        aoff[mf] = (uint32_t)(wm0 + mf * 16 + arow) * LDSZ + (uint32_t)ahalf;
#pragma unroll
    for (int nf = 0; nf < 4; nf++)
        boff[nf] = TILE_BYTES + (uint32_t)(wn0 + nf * 8 + brow) * LDSZ + (uint32_t)bhalf;

    // per-thread load mapping: 4 chunks A + 4 chunks B (1024 chunks of 16B each)
    auto load_stage = [&](uint32_t st, int k0) {
        const uint32_t base = smem0 + st * STAGE_BYTES;
#pragma unroll
        for (int i = 0; i < 4; i++) {
            int cc = tid + i * 256;
            int row = cc >> 3, col = (cc & 7) << 4;
            cp16(base + (uint32_t)row * LDSZ + (uint32_t)col,
                 &g_xq[(size_t)(m0 + row) * DIM + k0 + col]);
        }
#pragma unroll
        for (int i = 0; i < 4; i++) {
            int cc = tid + i * 256;
            int row = cc >> 3, col = (cc & 7) << 4;
            cp16(base + TILE_BYTES + (uint32_t)row * LDSZ + (uint32_t)col,
                 &g_Wq[(size_t)(n0 + row) * DIM + k0 + col]);
        }
        asm volatile("cp.async.commit_group;\n");
    };

    load_stage(0u, 0);

    for (int kt = 0; kt < NKT; kt++) {
        asm volatile("cp.async.wait_group 0;\n");
        __syncthreads();
        if (kt + 1 < NKT) load_stage((uint32_t)((kt + 1) & 1), (kt + 1) * KS);

        const uint32_t base = smem0 + (uint32_t)(kt & 1) * STAGE_BYTES;
#pragma unroll
        for (int kk = 0; kk < 4; kk++) {  // four k32 steps per 128B stage
            uint32_t a[4][4], b[4][2];
#pragma unroll
            for (int mf = 0; mf < 4; mf++) {
                uint32_t addr = base + aoff[mf] + (uint32_t)(kk * 32);
                asm volatile("ldmatrix.sync.aligned.m8n8.x4.shared.b16 {%0,%1,%2,%3}, [%4];\n"
                             : "=r"(a[mf][0]), "=r"(a[mf][1]), "=r"(a[mf][2]), "=r"(a[mf][3])
                             : "r"(addr));
            }
#pragma unroll
            for (int nf = 0; nf < 4; nf++) {
                uint32_t addr = base + boff[nf] + (uint32_t)(kk * 32);
                asm volatile("ldmatrix.sync.aligned.m8n8.x2.shared.b16 {%0,%1}, [%2];\n"
                             : "=r"(b[nf][0]), "=r"(b[nf][1])
                             : "r"(addr));
            }
#pragma unroll
            for (int mf = 0; mf < 4; mf++)
#pragma unroll
                for (int nf = 0; nf < 4; nf++) {
                    asm volatile(
                        "mma.sync.aligned.m16n8k32.row.col.f32.e4m3.e4m3.f32 "
                        "{%0,%1,%2,%3}, {%4,%5,%6,%7}, {%8,%9}, {%0,%1,%2,%3};\n"
                        : "+f"(c[mf][nf][0]), "+f"(c[mf][nf][1]),
                          "+f"(c[mf][nf][2]), "+f"(c[mf][nf][3])
                        : "r"(a[mf][0]), "r"(a[mf][1]), "r"(a[mf][2]), "r"(a[mf][3]),
                          "r"(b[nf][0]), "r"(b[nf][1]));
                }
        }
    }
    __syncthreads();

    // fused epilogue: per-row sum(exp(logit)), sum(logit); logit = c/256.
    float* redE = reinterpret_cast<float*>(dsm + RED_OFF);           // [128][4]
    float* redL = reinterpret_cast<float*>(dsm + RED_OFF + 2048);    // [128][4]
#pragma unroll
    for (int mf = 0; mf < 4; mf++)
#pragma unroll
        for (int r = 0; r < 2; r++) {
            float se = 0.f, sl = 0.f;
#pragma unroll
            for (int nf = 0; nf < 4; nf++)
#pragma unroll
                for (int j = 0; j < 2; j++) {
                    float v = c[mf][nf][r * 2 + j] * INV_SCALE;
                    se += __expf(v);
                    sl += v;
                }
            se += __shfl_xor_sync(0xffffffffu, se, 1);
            sl += __shfl_xor_sync(0xffffffffu, sl, 1);
            se += __shfl_xor_sync(0xffffffffu, se, 2);
            sl += __shfl_xor_sync(0xffffffffu, sl, 2);
            if ((lane & 3) == 0) {
                int row = wm0 + mf * 16 + r * 8 + (lane >> 2);
                redE[row * 4 + wn] = se;
                redL[row * 4 + wn] = sl;
            }
        }
    __syncthreads();
    if (tid < 128) {
        float e = redE[tid * 4 + 0] + redE[tid * 4 + 1] + redE[tid * 4 + 2] + redE[tid * 4 + 3];
        float l = redL[tid * 4 + 0] + redL[tid * 4 + 1] + redL[tid * 4 + 2] + redL[tid * 4 + 3];
        g_pExp[(size_t)ct * NROWS + m0 + tid] = e;
        g_pLog[(size_t)ct * NROWS + m0 + tid] = l;
    }
}

// ---------------- gathered target logit, fp32 exact path ----------------
__global__ void gatherdot_kernel(const float* __restrict__ x,
                                 const float* __restrict__ W,
                                 const int* __restrict__ y32) {
    int n = blockIdx.x, tid = threadIdx.x;  // 128 threads
    bool is64 = (y32[1] == 0) && (y32[3] == 0) && (y32[5] == 0) && (y32[7] == 0);
    int idx = is64 ? y32[2 * n] : y32[n];
    if (idx < 0) idx = 0;
    if (idx >= VOCAB) idx = VOCAB - 1;
    const float* xr = x + (size_t)n * DIM;
    const float* wr = W + (size_t)idx * DIM;
    float s = 0.f;
    for (int d = tid; d < DIM; d += 128) s += xr[d] * wr[d];
#pragma unroll
    for (int o = 16; o; o >>= 1) s += __shfl_xor_sync(0xffffffffu, s, o);
    __shared__ float sm[4];
    if ((tid & 31) == 0) sm[tid >> 5] = s;
    __syncthreads();
    if (tid == 0) g_ly[n] = sm[0] + sm[1] + sm[2] + sm[3];
}

// ---------------- per-row reduce over column tiles ----------------
__global__ void rowreduce_kernel() {
    int n = blockIdx.x * 256 + threadIdx.x;
    float e = 0.f, l = 0.f;
    for (int t = 0; t < CTILES; t++) {
        e += g_pExp[(size_t)t * NROWS + n];
        l += g_pLog[(size_t)t * NROWS + n];
    }
    g_rv[n] = logf(e) - (1.0f - SMOOTH) * g_ly[n] - (SMOOTH / (float)VOCAB) * l;
}

// ---------------- deterministic final scalar reduce ----------------
__global__ void final_kernel(float* __restrict__ out) {
    int tid = threadIdx.x;
    double s = 0.0;
    for (int i = tid; i < NROWS; i += 1024) s += (double)g_rv[i];
#pragma unroll
    for (int o = 16; o; o >>= 1) s += __shfl_xor_sync(0xffffffffu, s, o);
    __shared__ double sm[32];
    if ((tid & 31) == 0) sm[tid >> 5] = s;
    __syncthreads();
    if (tid < 32) {
        double v = sm[tid];
#pragma unroll
        for (int o = 16; o; o >>= 1) v += __shfl_xor_sync(0xffffffffu, v, o);
        if (tid == 0) out[0] = (float)(v / (double)NROWS);
    }
}

extern "C" void kernel_launch(void* const* d_in, const int* in_sizes, int n_in,
                              void* d_out, int out_size) {
    const float* x = nullptr;
    const float* W = nullptr;
    const int*   y = nullptr;
    for (int i = 0; i < n_in; i++) {
        if (in_sizes[i] == VOCAB * DIM)      W = (const float*)d_in[i];
        else if (in_sizes[i] == NROWS * DIM) x = (const float*)d_in[i];
        else if (in_sizes[i] == NROWS)       y = (const int*)d_in[i];
    }

    cudaFuncSetAttribute(gemm_lse_kernel,
                         cudaFuncAttributeMaxDynamicSharedMemorySize, SMEM_DYN);

    gatherdot_kernel<<<NROWS, 128>>>(x, W, y);
    cvt_x_kernel<<<(NROWS * DIM) / (256 * 4), 256>>>(x);
    cvt_w_kernel<<<(VOCAB * DIM) / (256 * 4), 256>>>(W);
    gemm_lse_kernel<<<dim3(CTILES, RTILES), 256, SMEM_DYN>>>();
    rowreduce_kernel<<<NROWS / 256, 256>>>();
    final_kernel<<<1, 1024>>>((float*)d_out);
}